// round 3
// baseline (speedup 1.0000x reference)
#include <cuda_runtime.h>
#include <cuda_fp16.h>
#include <cstddef>

#define D 64
#define NH 4
#define DH 16
#define FF 2048
#define VV 1000000
#define STEPS 10
#define EPS 1e-5f
#define NB 296  // 2 blocks/SM on 148+ SMs -> all resident, barrier-safe

// Persistent device state (zero-init at load; everything re-derived each call).
__device__ float g_x1[STEPS * D];
__device__ float g_y[STEPS * D];
__device__ unsigned long long g_amax[STEPS];
__device__ int g_gen[STEPS];
__device__ uint4 g_embh4[VV * 8];  // 128MB fp16 emb copy (written in step 0)
__device__ int g_cnt;              // barrier counter (self-resetting)
__device__ int g_genbar;           // barrier generation (monotonic)

__device__ __forceinline__ unsigned int fkey(float f) {
    unsigned int u = __float_as_uint(f);
    return (u & 0x80000000u) ? ~u : (u | 0x80000000u);
}
__device__ __forceinline__ int dec_idx(unsigned long long k) {
    return (int)(0xFFFFFFFFu - (unsigned int)(k & 0xFFFFFFFFull));
}
__device__ __forceinline__ float dot4(float4 a, float4 b) {
    return a.x * b.x + a.y * b.y + a.z * b.z + a.w * b.w;
}
__device__ __forceinline__ uint4 pack8(float4 a, float4 b) {
    uint4 o;
    __half2 h;
    h = __floats2half2_rn(a.x, a.y); o.x = *(unsigned int*)&h;
    h = __floats2half2_rn(a.z, a.w); o.y = *(unsigned int*)&h;
    h = __floats2half2_rn(b.x, b.y); o.z = *(unsigned int*)&h;
    h = __floats2half2_rn(b.z, b.w); o.w = *(unsigned int*)&h;
    return o;
}
__device__ __forceinline__ float dot8h(uint4 q, float4 xa, float4 xb) {
    __half2* hp = (__half2*)&q;
    float2 f0 = __half22float2(hp[0]), f1 = __half22float2(hp[1]);
    float2 f2 = __half22float2(hp[2]), f3 = __half22float2(hp[3]);
    return f0.x * xa.x + f0.y * xa.y + f1.x * xa.z + f1.y * xa.w
         + f2.x * xb.x + f2.y * xb.y + f3.x * xb.z + f3.y * xb.w;
}

// Grid-wide barrier: all NB blocks resident by construction.
__device__ __forceinline__ void grid_bar() {
    __syncthreads();
    if (threadIdx.x == 0) {
        volatile int* genp = &g_genbar;
        int gen = *genp;
        __threadfence();
        if (atomicAdd(&g_cnt, 1) == (int)gridDim.x - 1) {
            atomicExch(&g_cnt, 0);
            __threadfence();
            *genp = gen + 1;
        } else {
            while (*genp == gen) { __nanosleep(32); }
        }
    }
    __syncthreads();
}

// ---------------------------------------------------------------------------
// Attention phase (block 0 only, 256 threads).
// ---------------------------------------------------------------------------
__device__ void attn_phase(const float* __restrict__ ht,
                           const float* __restrict__ emb,
                           const float* __restrict__ pos,
                           const float* __restrict__ ipw,
                           const float* __restrict__ ipb,
                           const float* __restrict__ ow,
                           const float* __restrict__ ob,
                           const float* __restrict__ ln1w,
                           const float* __restrict__ ln1b,
                           const float* __restrict__ ln2w,
                           const float* __restrict__ ln2b,
                           const float* __restrict__ f2b,
                           int layer, int S, int t,
                           float* x, float* qkv, float* o, float* sc,
                           float* stat) {
    int tid = threadIdx.x;
    const int nt = 256;

    if (layer == 0) {
        if (tid == 0) {
            if (t > 0) {
                long long a = __ldcg((const long long*)&g_amax[t - 1]);
                g_gen[t - 1] = dec_idx((unsigned long long)a);
            }
            atomicExch(&g_amax[t], 0ull);
        }
        __syncthreads();
        for (int i = tid; i < S * D; i += nt) {
            int s = i >> 6, d = i & 63;
            float base = (s == 0) ? ht[d] : emb[(size_t)g_gen[s - 1] * D + d];
            x[i] = base + pos[i];
        }
    } else {
        for (int i = tid; i < S * D; i += nt)
            x[i] = __ldcg(&g_x1[i]) + __ldcg(&g_y[i]);
        __syncthreads();
        if (tid < S) {
            float m = 0.f;
            for (int d = 0; d < D; d++) m += x[tid * D + d];
            m *= (1.f / D);
            float vv = 0.f;
            for (int d = 0; d < D; d++) { float df = x[tid * D + d] - m; vv += df * df; }
            vv *= (1.f / D);
            stat[tid * 2] = m;
            stat[tid * 2 + 1] = rsqrtf(vv + EPS);
        }
        __syncthreads();
        for (int i = tid; i < S * D; i += nt) {
            int s = i >> 6, d = i & 63;
            x[i] = (x[i] - stat[s * 2]) * stat[s * 2 + 1] * ln2w[d] + ln2b[d];
        }
    }
    __syncthreads();

    // qkv = x @ ipw^T + ipb
    const float* W = ipw + (size_t)layer * 3 * D * D;
    const float* B = ipb + layer * 3 * D;
    for (int i = tid; i < S * 3 * D; i += nt) {
        int s = i / (3 * D), j = i % (3 * D);
        const float4* wr = (const float4*)(W + (size_t)j * D);
        const float4* xr = (const float4*)(x + s * D);
        float acc = B[j];
#pragma unroll
        for (int k = 0; k < 16; k++) acc += dot4(wr[k], xr[k]);
        qkv[i] = acc;
    }
    __syncthreads();

    for (int i = tid; i < NH * S * S; i += nt) {
        int h = i / (S * S), r = (i / S) % S, c = i % S;
        const float* q = qkv + r * 3 * D + h * DH;
        const float* k = qkv + c * 3 * D + D + h * DH;
        float acc = 0.f;
#pragma unroll
        for (int d = 0; d < DH; d++) acc += q[d] * k[d];
        sc[(h * S + r) * S + c] = acc * 0.25f;
    }
    __syncthreads();

    for (int i = tid; i < NH * S; i += nt) {
        float* row = sc + i * S;
        float mx = row[0];
        for (int c = 1; c < S; c++) mx = fmaxf(mx, row[c]);
        float sm = 0.f;
        for (int c = 0; c < S; c++) { float e = expf(row[c] - mx); row[c] = e; sm += e; }
        float inv = 1.f / sm;
        for (int c = 0; c < S; c++) row[c] *= inv;
    }
    __syncthreads();

    for (int i = tid; i < S * D; i += nt) {
        int s = i >> 6, col = i & 63;
        int h = col >> 4, d = col & 15;
        const float* a = sc + (h * S + s) * S;
        float acc = 0.f;
        for (int c = 0; c < S; c++) acc += a[c] * qkv[c * 3 * D + 2 * D + h * DH + d];
        o[i] = acc;
    }
    __syncthreads();

    const float* OW = ow + (size_t)layer * D * D;
    const float* OB = ob + layer * D;
    for (int i = tid; i < S * D; i += nt) {
        int s = i >> 6, e = i & 63;
        const float4* wr = (const float4*)(OW + (size_t)e * D);
        const float4* orow = (const float4*)(o + s * D);
        float acc = OB[e];
#pragma unroll
        for (int k2 = 0; k2 < 16; k2++) acc += dot4(wr[k2], orow[k2]);
        qkv[i] = x[i] + acc;
    }
    __syncthreads();
    if (tid < S) {
        float m = 0.f;
        for (int d = 0; d < D; d++) m += qkv[tid * D + d];
        m *= (1.f / D);
        float vv = 0.f;
        for (int d = 0; d < D; d++) { float df = qkv[tid * D + d] - m; vv += df * df; }
        vv *= (1.f / D);
        stat[tid * 2] = m;
        stat[tid * 2 + 1] = rsqrtf(vv + EPS);
    }
    __syncthreads();
    const float* L1W = ln1w + layer * D;
    const float* L1B = ln1b + layer * D;
    for (int i = tid; i < S * D; i += nt) {
        int s = i >> 6, d = i & 63;
        float v = (qkv[i] - stat[s * 2]) * stat[s * 2 + 1] * L1W[d] + L1B[d];
        __stcg(&g_x1[i], v);
        __stcg(&g_y[i], f2b[layer * D + d]);  // seed FFN output with bias
    }
}

// ---------------------------------------------------------------------------
// FFN phase (blocks 0..63, 32 FF units each).
// ---------------------------------------------------------------------------
__device__ void ffn_phase(const float* __restrict__ f1w,
                          const float* __restrict__ f1b,
                          const float* __restrict__ f2w,
                          int layer, int S, float* xs, float* hsm) {
    int tid = threadIdx.x;
    for (int i = tid; i < S * D; i += 256) xs[i] = __ldcg(&g_x1[i]);
    __syncthreads();

    int g = tid >> 3, l = tid & 7;
    int f = blockIdx.x * 32 + g;
    const float4* w1r = (const float4*)(f1w + (size_t)layer * FF * D + (size_t)f * D);
    float4 wa = w1r[l * 2], wb = w1r[l * 2 + 1];
    float b1 = f1b[layer * FF + f];
    const float4* xs4 = (const float4*)xs;
    for (int s = 0; s < S; s++) {
        float v = dot4(wa, xs4[s * 16 + l * 2]) + dot4(wb, xs4[s * 16 + l * 2 + 1]);
        v += __shfl_xor_sync(0xffffffffu, v, 4);
        v += __shfl_xor_sync(0xffffffffu, v, 2);
        v += __shfl_xor_sync(0xffffffffu, v, 1);
        if (l == 0) hsm[s * 32 + g] = fmaxf(v + b1, 0.f);
    }
    __syncthreads();

    int d = tid >> 2, q = tid & 3;
    const float4* w2r = (const float4*)(f2w + (size_t)layer * D * FF + (size_t)d * FF
                                        + blockIdx.x * 32);
    float4 va = w2r[q * 2], vb = w2r[q * 2 + 1];
    const float4* h4 = (const float4*)hsm;
    for (int s = 0; s < S; s++) {
        float r = dot4(va, h4[s * 8 + q * 2]) + dot4(vb, h4[s * 8 + q * 2 + 1]);
        r += __shfl_xor_sync(0xffffffffu, r, 1);
        r += __shfl_xor_sync(0xffffffffu, r, 2);
        if (q == 0) atomicAdd(&g_y[s * 64 + d], r);
    }
}

// ---------------------------------------------------------------------------
// Logits phase (all blocks). t==0 reads fp32 emb + writes fp16 copy;
// t>0 scans fp16 copy. 4-row ILP per 8-lane group.
// ---------------------------------------------------------------------------
__device__ void logits_phase(const float* __restrict__ emb,
                             const float* __restrict__ ln2w,
                             const float* __restrict__ ln2b,
                             float* __restrict__ out, int t, int S,
                             float* xr, float* xs, float* stat,
                             unsigned long long* bs) {
    int tid = threadIdx.x;
    if (tid < D) xr[tid] = __ldcg(&g_x1[(S - 1) * D + tid]) + __ldcg(&g_y[(S - 1) * D + tid]);
    __syncthreads();
    if (tid == 0) {
        float m = 0.f;
        for (int d = 0; d < D; d++) m += xr[d];
        m *= (1.f / D);
        float vv = 0.f;
        for (int d = 0; d < D; d++) { float df = xr[d] - m; vv += df * df; }
        vv *= (1.f / D);
        stat[0] = m;
        stat[1] = rsqrtf(vv + EPS);
    }
    __syncthreads();
    if (tid < D)
        xs[tid] = (xr[tid] - stat[0]) * stat[1] * ln2w[D + tid] + ln2b[D + tid];
    __syncthreads();

    const float4* xs4 = (const float4*)xs;
    int lane = tid & 31, wid = tid >> 5;
    int grp = lane >> 3, l8 = lane & 7;
    float4 xa = xs4[2 * l8], xb = xs4[2 * l8 + 1];
    unsigned long long best = 0ull;
    float* orow = out + (size_t)t * VV;

    if (t == 0) {
        for (int base = blockIdx.x * 128; base < VV; base += gridDim.x * 128) {
            int v0 = base + wid * 16 + grp * 4;
            if (v0 >= VV) continue;
            float4 av[4], bv[4];
#pragma unroll
            for (int r = 0; r < 4; r++) {
                const float4* p = (const float4*)(emb + (size_t)(v0 + r) * D);
                av[r] = __ldcg(p + 2 * l8);
                bv[r] = __ldcg(p + 2 * l8 + 1);
            }
#pragma unroll
            for (int r = 0; r < 4; r++) {
                int v = v0 + r;
                g_embh4[(size_t)v * 8 + l8] = pack8(av[r], bv[r]);
                float dot = dot4(av[r], xa) + dot4(bv[r], xb);
                dot += __shfl_xor_sync(0xffffffffu, dot, 1);
                dot += __shfl_xor_sync(0xffffffffu, dot, 2);
                dot += __shfl_xor_sync(0xffffffffu, dot, 4);
                if (l8 == 0) {
                    orow[v] = dot;
                    unsigned long long key =
                        ((unsigned long long)fkey(dot) << 32) | (0xFFFFFFFFu - (unsigned)v);
                    if (key > best) best = key;
                }
            }
        }
    } else {
        for (int base = blockIdx.x * 128; base < VV; base += gridDim.x * 128) {
            int v0 = base + wid * 16 + grp * 4;
            if (v0 >= VV) continue;
            uint4 qq[4];
#pragma unroll
            for (int r = 0; r < 4; r++)
                qq[r] = __ldcg(&g_embh4[(size_t)(v0 + r) * 8 + l8]);
#pragma unroll
            for (int r = 0; r < 4; r++) {
                float dot = dot8h(qq[r], xa, xb);
                dot += __shfl_xor_sync(0xffffffffu, dot, 1);
                dot += __shfl_xor_sync(0xffffffffu, dot, 2);
                dot += __shfl_xor_sync(0xffffffffu, dot, 4);
                if (l8 == 0) {
                    int v = v0 + r;
                    orow[v] = dot;
                    unsigned long long key =
                        ((unsigned long long)fkey(dot) << 32) | (0xFFFFFFFFu - (unsigned)v);
                    if (key > best) best = key;
                }
            }
        }
    }

    bs[tid] = best;
    __syncthreads();
    for (int o2 = 128; o2; o2 >>= 1) {
        if (tid < o2) { if (bs[tid + o2] > bs[tid]) bs[tid] = bs[tid + o2]; }
        __syncthreads();
    }
    if (tid == 0) atomicMax(&g_amax[t], bs[0]);
}

// ---------------------------------------------------------------------------
__global__ void __launch_bounds__(256, 2)
persist_kernel(const float* __restrict__ ht, const float* __restrict__ emb,
               const float* __restrict__ pos, const float* __restrict__ ipw,
               const float* __restrict__ ipb, const float* __restrict__ ow,
               const float* __restrict__ ob, const float* __restrict__ ln1w,
               const float* __restrict__ ln1b, const float* __restrict__ ln2w,
               const float* __restrict__ ln2b, const float* __restrict__ f1w,
               const float* __restrict__ f1b, const float* __restrict__ f2w,
               const float* __restrict__ f2b, float* __restrict__ out,
               int out_size) {
    __shared__ __align__(16) float sx[STEPS * D];
    __shared__ __align__(16) float sqkv[STEPS * 3 * D];
    __shared__ __align__(16) float so[STEPS * D];
    __shared__ float ssc[NH * STEPS * STEPS];
    __shared__ float sstat[2 * STEPS];
    __shared__ unsigned long long sbs[256];

    for (int t = 0; t < STEPS; t++) {
        int S = t + 1;
        if (blockIdx.x == 0)
            attn_phase(ht, emb, pos, ipw, ipb, ow, ob, ln1w, ln1b, ln2w, ln2b,
                       f2b, 0, S, t, sx, sqkv, so, ssc, sstat);
        grid_bar();
        if (blockIdx.x < 64) ffn_phase(f1w, f1b, f2w, 0, S, sx, so);
        grid_bar();
        if (blockIdx.x == 0)
            attn_phase(ht, emb, pos, ipw, ipb, ow, ob, ln1w, ln1b, ln2w, ln2b,
                       f2b, 1, S, t, sx, sqkv, so, ssc, sstat);
        grid_bar();
        if (blockIdx.x < 64) ffn_phase(f1w, f1b, f2w, 1, S, sx, so);
        grid_bar();
        logits_phase(emb, ln2w, ln2b, out, t, S, sx, so, sstat, sbs);
        grid_bar();
    }

    if (blockIdx.x == 0 && threadIdx.x == 0) {
        long long a = __ldcg((const long long*)&g_amax[STEPS - 1]);
        g_gen[STEPS - 1] = dec_idx((unsigned long long)a);
        if (out_size >= STEPS * VV + STEPS)
            for (int i = 0; i < STEPS; i++)
                out[(size_t)STEPS * VV + i] = (float)g_gen[i];
    }
}

extern "C" void kernel_launch(void* const* d_in, const int* in_sizes, int n_in,
                              void* d_out, int out_size) {
    const float* ht  = (const float*)d_in[0];
    const float* emb = (const float*)d_in[1];
    const float* pos = (const float*)d_in[2];
    const float* ipw = (const float*)d_in[3];
    const float* ipb = (const float*)d_in[4];
    const float* ow  = (const float*)d_in[5];
    const float* ob  = (const float*)d_in[6];
    const float* l1w = (const float*)d_in[7];
    const float* l1b = (const float*)d_in[8];
    const float* l2w = (const float*)d_in[9];
    const float* l2b = (const float*)d_in[10];
    const float* f1w = (const float*)d_in[11];
    const float* f1b = (const float*)d_in[12];
    const float* f2w = (const float*)d_in[13];
    const float* f2b = (const float*)d_in[14];
    float* out = (float*)d_out;

    persist_kernel<<<NB, 256>>>(ht, emb, pos, ipw, ipb, ow, ob, l1w, l1b,
                                l2w, l2b, f1w, f1b, f2w, f2b, out, out_size);
}

// round 4
// speedup vs baseline: 1.1687x; 1.1687x over previous
#include <cuda_runtime.h>
#include <cuda_fp16.h>
#include <cstddef>

#define D 64
#define NH 4
#define DH 16
#define FF 2048
#define VV 1000000
#define STEPS 10
#define EPS 1e-5f
#define NB 148
#define NT 512

// Persistent device state.
__device__ float g_x1[STEPS * D];            // layer-0 post-LN1 (all rows)
__device__ float g_y0[STEPS * D];            // ffn0 accumulator (all rows)
__device__ float g_x1b[D];                   // layer-1 post-LN1 (last row)
__device__ float g_y1[D];                    // ffn1 accumulator (last row)
__device__ unsigned long long g_amax[STEPS]; // packed argmax
__device__ int g_gen[STEPS];
__device__ uint4 g_embh4[VV * 8];            // fp16 emb copy (written step 0)
__device__ int g_cnt;
__device__ int g_genbar;

__device__ __forceinline__ unsigned int fkey(float f) {
    unsigned int u = __float_as_uint(f);
    return (u & 0x80000000u) ? ~u : (u | 0x80000000u);
}
__device__ __forceinline__ int dec_idx(unsigned long long k) {
    return (int)(0xFFFFFFFFu - (unsigned int)(k & 0xFFFFFFFFull));
}
__device__ __forceinline__ float dot4(float4 a, float4 b) {
    return a.x * b.x + a.y * b.y + a.z * b.z + a.w * b.w;
}
__device__ __forceinline__ uint4 pack8(float4 a, float4 b) {
    uint4 o;
    __half2 h;
    h = __floats2half2_rn(a.x, a.y); o.x = *(unsigned int*)&h;
    h = __floats2half2_rn(a.z, a.w); o.y = *(unsigned int*)&h;
    h = __floats2half2_rn(b.x, b.y); o.z = *(unsigned int*)&h;
    h = __floats2half2_rn(b.z, b.w); o.w = *(unsigned int*)&h;
    return o;
}
__device__ __forceinline__ float dot8h(uint4 q, float4 xa, float4 xb) {
    __half2* hp = (__half2*)&q;
    float2 f0 = __half22float2(hp[0]), f1 = __half22float2(hp[1]);
    float2 f2 = __half22float2(hp[2]), f3 = __half22float2(hp[3]);
    return f0.x * xa.x + f0.y * xa.y + f1.x * xa.z + f1.y * xa.w
         + f2.x * xb.x + f2.y * xb.y + f3.x * xb.z + f3.y * xb.w;
}
__device__ __forceinline__ float red8(float v) {
    v += __shfl_xor_sync(0xffffffffu, v, 4);
    v += __shfl_xor_sync(0xffffffffu, v, 2);
    v += __shfl_xor_sync(0xffffffffu, v, 1);
    return v;
}

// Grid barrier: all NB blocks resident (1 CTA/SM).
__device__ __forceinline__ void grid_bar() {
    __syncthreads();
    if (threadIdx.x == 0) {
        volatile int* genp = &g_genbar;
        int gen = *genp;
        __threadfence();
        if (atomicAdd(&g_cnt, 1) == NB - 1) {
            atomicExch(&g_cnt, 0);
            __threadfence();
            *genp = gen + 1;
        } else {
            while (*genp == gen) { __nanosleep(32); }
        }
    }
    __syncthreads();
}

__global__ void __launch_bounds__(NT, 1)
persist_kernel(const float* __restrict__ ht, const float* __restrict__ emb,
               const float* __restrict__ pos, const float* __restrict__ ipw,
               const float* __restrict__ ipb, const float* __restrict__ ow,
               const float* __restrict__ ob, const float* __restrict__ ln1w,
               const float* __restrict__ ln1b, const float* __restrict__ ln2w,
               const float* __restrict__ ln2b, const float* __restrict__ f1w,
               const float* __restrict__ f1b, const float* __restrict__ f2w,
               const float* __restrict__ f2b, float* __restrict__ out,
               int out_size) {
    __shared__ __align__(16) float sA[STEPS * D];      // x / x1 / hsm input
    __shared__ __align__(16) float sQ[STEPS * 3 * D];  // qkv / residual scratch
    __shared__ __align__(16) float sO[STEPS * D];      // attn out / ffn hidden
    __shared__ float sSC[NH * STEPS * STEPS];
    __shared__ float sST[2 * STEPS + 4];
    __shared__ int sgen[STEPS];
    __shared__ unsigned long long sbs[NT];

    const int tid = threadIdx.x, blk = blockIdx.x;
    const int lane = tid & 31, wrp = tid >> 5;
    const int grp = lane >> 3, l8 = lane & 7;
    const int g8 = tid >> 3, r8 = tid & 7;  // 64 groups of 8 lanes

    // Init: zero accumulators (block 0), then sync grid.
    if (blk == 0) {
        for (int i = tid; i < STEPS * D; i += NT) __stcg(&g_y0[i], 0.f);
        if (tid < D) __stcg(&g_y1[tid], 0.f);
    }
    grid_bar();

    for (int t = 0; t < STEPS; t++) {
        const int S = t + 1;

        // ================= P1: attn layer0 (redundant) + ffn0 (blocks 0..31)
        if (blk < 32) {
            if (tid < t) {
                int gi;
                if (tid == t - 1) {
                    unsigned long long a = __ldcg(&g_amax[t - 1]);
                    gi = dec_idx(a);
                    if (blk == 0) __stcg(&g_gen[t - 1], gi);
                } else {
                    gi = __ldcg(&g_gen[tid]);
                }
                sgen[tid] = gi;
            }
            if (blk == 0 && tid == 0) __stcg(&g_amax[t], 0ull);
            if (blk == 0 && tid < D) __stcg(&g_y1[tid], 0.f);  // for this step's P2
            __syncthreads();
            for (int i = tid; i < S * D; i += NT) {
                int s = i >> 6, d = i & 63;
                float base = (s == 0) ? ht[d] : emb[(size_t)sgen[s - 1] * D + d];
                sA[i] = base + pos[i];
            }
            __syncthreads();

            // qkv (layer 0)
            for (int i = tid; i < S * 3 * D; i += NT) {
                int s = i / 192, j = i % 192;
                const float4* wr = (const float4*)(ipw + (size_t)j * D);
                const float4* xr = (const float4*)(sA + s * D);
                float acc = ipb[j];
#pragma unroll
                for (int k = 0; k < 16; k++) acc += dot4(wr[k], xr[k]);
                sQ[i] = acc;
            }
            __syncthreads();
            for (int i = tid; i < NH * S * S; i += NT) {
                int h = i / (S * S), r = (i / S) % S, c = i % S;
                const float* q = sQ + r * 192 + h * DH;
                const float* k = sQ + c * 192 + D + h * DH;
                float acc = 0.f;
#pragma unroll
                for (int d = 0; d < DH; d++) acc += q[d] * k[d];
                sSC[(h * S + r) * S + c] = acc * 0.25f;
            }
            __syncthreads();
            if (tid < NH * S) {
                float* row = sSC + tid * S;
                float mx = row[0];
                for (int c = 1; c < S; c++) mx = fmaxf(mx, row[c]);
                float sm = 0.f;
                for (int c = 0; c < S; c++) { float e = expf(row[c] - mx); row[c] = e; sm += e; }
                float inv = 1.f / sm;
                for (int c = 0; c < S; c++) row[c] *= inv;
            }
            __syncthreads();
            for (int i = tid; i < S * D; i += NT) {
                int s = i >> 6, col = i & 63, h = col >> 4, d = col & 15;
                const float* a = sSC + (h * S + s) * S;
                float acc = 0.f;
                for (int c = 0; c < S; c++) acc += a[c] * sQ[c * 192 + 2 * D + h * DH + d];
                sO[i] = acc;
            }
            __syncthreads();
            for (int i = tid; i < S * D; i += NT) {
                int s = i >> 6, e = i & 63;
                const float4* wr = (const float4*)(ow + (size_t)e * D);
                const float4* orow = (const float4*)(sO + s * D);
                float acc = ob[e];
#pragma unroll
                for (int k = 0; k < 16; k++) acc += dot4(wr[k], orow[k]);
                sQ[i] = sA[i] + acc;
            }
            __syncthreads();
            if (tid < S) {
                float m = 0.f;
                for (int d = 0; d < D; d++) m += sQ[tid * D + d];
                m *= (1.f / D);
                float vv = 0.f;
                for (int d = 0; d < D; d++) { float df = sQ[tid * D + d] - m; vv += df * df; }
                vv *= (1.f / D);
                sST[tid * 2] = m;
                sST[tid * 2 + 1] = rsqrtf(vv + EPS);
            }
            __syncthreads();
            for (int i = tid; i < S * D; i += NT) {
                int s = i >> 6, d = i & 63;
                float v = (sQ[i] - sST[s * 2]) * sST[s * 2 + 1] * ln1w[d] + ln1b[d];
                sA[i] = v;
                if (blk == 0) __stcg(&g_x1[i], v);
            }
            __syncthreads();

            // ffn0: 64 units/block
            {
                int f = blk * 64 + g8;
                const float4* w1r = (const float4*)(f1w + (size_t)f * D);
                float4 wa = w1r[2 * r8], wb = w1r[2 * r8 + 1];
                float b1 = f1b[f];
                const float4* x4 = (const float4*)sA;
                for (int s = 0; s < S; s++) {
                    float v = red8(dot4(wa, x4[s * 16 + 2 * r8]) + dot4(wb, x4[s * 16 + 2 * r8 + 1]));
                    if (r8 == 0) sO[s * 64 + g8] = fmaxf(v + b1, 0.f);
                }
                __syncthreads();
                const float4* w2r = (const float4*)(f2w + (size_t)g8 * FF + blk * 64);
                float4 va = w2r[2 * r8], vb = w2r[2 * r8 + 1];
                const float4* h4 = (const float4*)sO;
                for (int s = 0; s < S; s++) {
                    float r = red8(dot4(va, h4[s * 16 + 2 * r8]) + dot4(vb, h4[s * 16 + 2 * r8 + 1]));
                    if (r8 == 0) {
                        if (blk == 0) r += f2b[g8];
                        atomicAdd(&g_y0[s * 64 + g8], r);
                    }
                }
            }
        }
        grid_bar();

        // ================= P2: attn layer1 last-row (redundant) + ffn1 (blocks 0..31)
        if (blk < 32) {
            for (int i = tid; i < S * D; i += NT)
                sA[i] = __ldcg(&g_x1[i]) + __ldcg(&g_y0[i]);
            __syncthreads();
            if (tid < S) {
                float m = 0.f;
                for (int d = 0; d < D; d++) m += sA[tid * D + d];
                m *= (1.f / D);
                float vv = 0.f;
                for (int d = 0; d < D; d++) { float df = sA[tid * D + d] - m; vv += df * df; }
                vv *= (1.f / D);
                sST[tid * 2] = m;
                sST[tid * 2 + 1] = rsqrtf(vv + EPS);
            }
            __syncthreads();
            for (int i = tid; i < S * D; i += NT) {
                int s = i >> 6, d = i & 63;
                sA[i] = (sA[i] - sST[s * 2]) * sST[s * 2 + 1] * ln2w[d] + ln2b[d];
            }
            __syncthreads();
            // qkv layer 1, all rows
            for (int i = tid; i < S * 3 * D; i += NT) {
                int s = i / 192, j = i % 192;
                const float4* wr = (const float4*)(ipw + (size_t)(192 + j) * D);
                const float4* xr = (const float4*)(sA + s * D);
                float acc = ipb[192 + j];
#pragma unroll
                for (int k = 0; k < 16; k++) acc += dot4(wr[k], xr[k]);
                sQ[i] = acc;
            }
            __syncthreads();
            // scores + softmax + o + proj, last row only
            if (tid < NH * S) {
                int h = tid / S, c = tid % S;
                const float* q = sQ + (S - 1) * 192 + h * DH;
                const float* k = sQ + c * 192 + D + h * DH;
                float acc = 0.f;
#pragma unroll
                for (int d = 0; d < DH; d++) acc += q[d] * k[d];
                sSC[h * S + c] = acc * 0.25f;
            }
            __syncthreads();
            if (tid < NH) {
                float* row = sSC + tid * S;
                float mx = row[0];
                for (int c = 1; c < S; c++) mx = fmaxf(mx, row[c]);
                float sm = 0.f;
                for (int c = 0; c < S; c++) { float e = expf(row[c] - mx); row[c] = e; sm += e; }
                float inv = 1.f / sm;
                for (int c = 0; c < S; c++) row[c] *= inv;
            }
            __syncthreads();
            if (tid < D) {
                int h = tid >> 4, d = tid & 15;
                const float* a = sSC + h * S;
                float acc = 0.f;
                for (int c = 0; c < S; c++) acc += a[c] * sQ[c * 192 + 2 * D + h * DH + d];
                sO[tid] = acc;
            }
            __syncthreads();
            if (tid < D) {
                const float4* wr = (const float4*)(ow + (size_t)(D + tid) * D);
                const float4* orow = (const float4*)sO;
                float acc = ob[D + tid];
#pragma unroll
                for (int k = 0; k < 16; k++) acc += dot4(wr[k], orow[k]);
                sQ[tid] = sA[(S - 1) * D + tid] + acc;
            }
            __syncthreads();
            if (tid == 0) {
                float m = 0.f;
                for (int d = 0; d < D; d++) m += sQ[d];
                m *= (1.f / D);
                float vv = 0.f;
                for (int d = 0; d < D; d++) { float df = sQ[d] - m; vv += df * df; }
                vv *= (1.f / D);
                sST[20] = m;
                sST[21] = rsqrtf(vv + EPS);
            }
            __syncthreads();
            if (tid < D) {
                float xl = (sQ[tid] - sST[20]) * sST[21] * ln1w[D + tid] + ln1b[D + tid];
                sA[tid] = xl;
                if (blk == 0) __stcg(&g_x1b[tid], xl);
            }
            __syncthreads();
            // ffn1 (layer 1), last row only
            {
                int f = blk * 64 + g8;
                const float4* w1r = (const float4*)(f1w + (size_t)FF * D + (size_t)f * D);
                float4 wa = w1r[2 * r8], wb = w1r[2 * r8 + 1];
                const float4* x4 = (const float4*)sA;
                float v = red8(dot4(wa, x4[2 * r8]) + dot4(wb, x4[2 * r8 + 1]));
                if (r8 == 0) sO[g8] = fmaxf(v + f1b[FF + f], 0.f);
                __syncthreads();
                const float4* w2r = (const float4*)(f2w + (size_t)D * FF + (size_t)g8 * FF + blk * 64);
                float4 va = w2r[2 * r8], vb = w2r[2 * r8 + 1];
                const float4* h4 = (const float4*)sO;
                float r = red8(dot4(va, h4[2 * r8]) + dot4(vb, h4[2 * r8 + 1]));
                if (r8 == 0) {
                    if (blk == 0) r += f2b[D + g8];
                    atomicAdd(&g_y1[g8], r);
                }
            }
        }
        grid_bar();

        // ================= P3: final LN (redundant) + logits scan (all blocks)
        if (tid < D) sA[tid] = __ldcg(&g_x1b[tid]) + __ldcg(&g_y1[tid]);
        __syncthreads();
        if (tid == 0) {
            float m = 0.f;
            for (int d = 0; d < D; d++) m += sA[d];
            m *= (1.f / D);
            float vv = 0.f;
            for (int d = 0; d < D; d++) { float df = sA[d] - m; vv += df * df; }
            vv *= (1.f / D);
            sST[0] = m;
            sST[1] = rsqrtf(vv + EPS);
        }
        __syncthreads();
        if (tid < D)
            sO[tid] = (sA[tid] - sST[0]) * sST[1] * ln2w[D + tid] + ln2b[D + tid];
        if (blk == 0)
            for (int i = tid; i < STEPS * D; i += NT) __stcg(&g_y0[i], 0.f);
        __syncthreads();

        const float4* xs4 = (const float4*)sO;
        float4 xa = xs4[2 * l8], xb = xs4[2 * l8 + 1];
        unsigned long long best = 0ull;
        float* orow = out + (size_t)t * VV;

        if (t == 0) {
            for (int base = blk * 256; base < VV; base += NB * 256) {
                int v0 = base + wrp * 16 + grp * 4;
                if (v0 >= VV) continue;
                float4 av[4], bv[4];
#pragma unroll
                for (int r = 0; r < 4; r++) {
                    const float4* p = (const float4*)(emb + (size_t)(v0 + r) * D);
                    av[r] = __ldcg(p + 2 * l8);
                    bv[r] = __ldcg(p + 2 * l8 + 1);
                }
#pragma unroll
                for (int r = 0; r < 4; r++) {
                    int v = v0 + r;
                    __stcg(&g_embh4[(size_t)v * 8 + l8], pack8(av[r], bv[r]));
                    float dot = dot4(av[r], xa) + dot4(bv[r], xb);
                    dot += __shfl_xor_sync(0xffffffffu, dot, 1);
                    dot += __shfl_xor_sync(0xffffffffu, dot, 2);
                    dot += __shfl_xor_sync(0xffffffffu, dot, 4);
                    if (l8 == 0) {
                        __stcg(&orow[v], dot);
                        unsigned long long key =
                            ((unsigned long long)fkey(dot) << 32) | (0xFFFFFFFFu - (unsigned)v);
                        if (key > best) best = key;
                    }
                }
            }
        } else {
            for (int base = blk * 512; base < VV; base += NB * 512) {
                int v0 = base + wrp * 32 + grp * 8;
                if (v0 >= VV) continue;
                uint4 qq[8];
#pragma unroll
                for (int r = 0; r < 8; r++)
                    qq[r] = __ldcg(&g_embh4[(size_t)(v0 + r) * 8 + l8]);
#pragma unroll
                for (int r = 0; r < 8; r++) {
                    float dot = dot8h(qq[r], xa, xb);
                    dot += __shfl_xor_sync(0xffffffffu, dot, 1);
                    dot += __shfl_xor_sync(0xffffffffu, dot, 2);
                    dot += __shfl_xor_sync(0xffffffffu, dot, 4);
                    if (l8 == 0) {
                        int v = v0 + r;
                        __stcg(&orow[v], dot);
                        unsigned long long key =
                            ((unsigned long long)fkey(dot) << 32) | (0xFFFFFFFFu - (unsigned)v);
                        if (key > best) best = key;
                    }
                }
            }
        }

        sbs[tid] = best;
        __syncthreads();
        for (int o2 = NT / 2; o2; o2 >>= 1) {
            if (tid < o2) { if (sbs[tid + o2] > sbs[tid]) sbs[tid] = sbs[tid + o2]; }
            __syncthreads();
        }
        if (tid == 0) atomicMax(&g_amax[t], sbs[0]);
        grid_bar();
    }

    if (blk == 0 && tid == 0) {
        unsigned long long a = __ldcg(&g_amax[STEPS - 1]);
        g_gen[STEPS - 1] = dec_idx(a);
        if (out_size >= STEPS * VV + STEPS)
            for (int i = 0; i < STEPS; i++)
                out[(size_t)STEPS * VV + i] = (float)__ldcg(&g_gen[i]);
    }
}

extern "C" void kernel_launch(void* const* d_in, const int* in_sizes, int n_in,
                              void* d_out, int out_size) {
    const float* ht  = (const float*)d_in[0];
    const float* emb = (const float*)d_in[1];
    const float* pos = (const float*)d_in[2];
    const float* ipw = (const float*)d_in[3];
    const float* ipb = (const float*)d_in[4];
    const float* ow  = (const float*)d_in[5];
    const float* ob  = (const float*)d_in[6];
    const float* l1w = (const float*)d_in[7];
    const float* l1b = (const float*)d_in[8];
    const float* l2w = (const float*)d_in[9];
    const float* l2b = (const float*)d_in[10];
    const float* f1w = (const float*)d_in[11];
    const float* f1b = (const float*)d_in[12];
    const float* f2w = (const float*)d_in[13];
    const float* f2b = (const float*)d_in[14];
    float* out = (float*)d_out;

    persist_kernel<<<NB, NT>>>(ht, emb, pos, ipw, ipb, ow, ob, l1w, l1b,
                               l2w, l2b, f1w, f1b, f2w, f2b, out, out_size);
}